// round 16
// baseline (speedup 1.0000x reference)
#include <cuda_runtime.h>
#include <cuda_bf16.h>

// Problem shape (fixed by the dataset)
#define Bv 8
#define Cv 256
#define Lv 4096
#define Kv 8
#define TPB 512
#define NJ (Lv / 4)       // float4s per row = 1024
#define ITERS (NJ / TPB)  // 2

// Precomputed per-(b,l) weight data (channel-independent, L2-resident):
//   g_E[b][j]   : float4 of E[l] = exp(dt[l]) for l = 4j..4j+3
//   g_inv[b][j] : float4 of 1/den[l], den[l] = sum_{k=0..7} E[l-k]
__device__ float4 g_E[Bv * NJ];
__device__ float4 g_inv[Bv * NJ];

// ---------------------------------------------------------------------------
// Precompute kernel. softmax identity: w_k(l) = E[l-k]/den[l] (base exp
// cancels; dt in [0,1) so no max-shift needed). l<7 values are don't-care
// (masked downstream).
// ---------------------------------------------------------------------------
__global__ void __launch_bounds__(128) precompute_kernel(const float* __restrict__ dt) {
    const int j  = blockIdx.x * 128 + threadIdx.x;   // 0 .. Bv*NJ-1
    const int jr = j & (NJ - 1);
    const float4* dtr = (const float4*)dt;
    const float4 z = make_float4(0.f, 0.f, 0.f, 0.f);

    float4 m2 = (jr >= 2) ? dtr[j - 2] : z;
    float4 m1 = (jr >= 1) ? dtr[j - 1] : z;
    float4 d0 = dtr[j];
    float Ew[12] = {m2.x, m2.y, m2.z, m2.w,
                    m1.x, m1.y, m1.z, m1.w,
                    d0.x, d0.y, d0.z, d0.w};
#pragma unroll
    for (int m = 0; m < 12; m++) Ew[m] = __expf(Ew[m]);

    float c45  = Ew[4] + Ew[5];
    float c67  = Ew[6] + Ew[7];
    float core = (c45 + c67) + Ew[8];          // E[4..8]
    float s23  = Ew[2] + Ew[3];
    float s910 = Ew[9] + Ew[10];
    float4 iv;
    iv.x = __fdividef(1.0f, core + (Ew[1] + s23));    // E[1..8]
    iv.y = __fdividef(1.0f, core + (s23 + Ew[9]));    // E[2..9]
    iv.z = __fdividef(1.0f, core + (Ew[3] + s910));   // E[3..10]
    iv.w = __fdividef(1.0f, core + (s910 + Ew[11]));  // E[4..11]

    g_E[j]   = make_float4(Ew[8], Ew[9], Ew[10], Ew[11]);
    g_inv[j] = iv;
}

// ---------------------------------------------------------------------------
// Fused kernel: one CTA per (b,c) row, 512 threads, 2 CTAs/SM (32 warps).
// at/ap live ENTIRELY in registers (same thread computes and emits each j);
// only 3 Gram scalars cross the barrier. No bulk smem, no STS/LDS round-trip.
//   num_c = sum_{m=c+1}^{c+8} E[m]*x[m] (windowed shared products)
//   at = num * inv;  at[l<7] = 0 exactly (reference BIG sentinel)
//   ap = sum_k kt[k] x[l-k]
//   out = ca*at + cb*ap with scalar ca,cb from the 2x2 Gram softmax.
// ---------------------------------------------------------------------------
template<bool FIRST>
__device__ __forceinline__ void pass1_iter(
    const int j,
    const float4* __restrict__ Er,
    const float4* __restrict__ ivr,
    const float4* __restrict__ xr,
    const float*  __restrict__ ktr,     // [Kv] in registers
    float*  __restrict__ gr,            // [3] Gram accumulators
    float4& atv_o, float4& apv_o)
{
    const float4 zero4 = make_float4(0.f, 0.f, 0.f, 0.f);

    float4 em2 = FIRST ? ((j >= 2) ? Er[j - 2] : zero4) : Er[j - 2];
    float4 em1 = FIRST ? ((j >= 1) ? Er[j - 1] : zero4) : Er[j - 1];
    float4 e0  = Er[j];
    float Ew[12] = {em2.x, em2.y, em2.z, em2.w,
                    em1.x, em1.y, em1.z, em1.w,
                    e0.x,  e0.y,  e0.z,  e0.w};
    float4 ivv = ivr[j];

    float4 xm2 = FIRST ? ((j >= 2) ? xr[j - 2] : zero4) : xr[j - 2];
    float4 xm1 = FIRST ? ((j >= 1) ? xr[j - 1] : zero4) : xr[j - 1];
    float4 x0  = xr[j];
    float xw[12] = {xm2.x, xm2.y, xm2.z, xm2.w,
                    xm1.x, xm1.y, xm1.z, xm1.w,
                    x0.x,  x0.y,  x0.z,  x0.w};

    // products p[m] = E[m]*x[m]; windowed numerators (shared core)
    float num[4];
    {
        float p1 = Ew[1] * xw[1],  p2 = Ew[2] * xw[2],  p3 = Ew[3] * xw[3];
        float p4 = Ew[4] * xw[4],  p5 = Ew[5] * xw[5],  p6 = Ew[6] * xw[6];
        float p7 = Ew[7] * xw[7],  p8 = Ew[8] * xw[8],  p9 = Ew[9] * xw[9];
        float p10 = Ew[10] * xw[10], p11 = Ew[11] * xw[11];
        float c45  = p4 + p5;
        float c67  = p6 + p7;
        float core = (c45 + c67) + p8;         // p[4..8]
        float s23  = p2 + p3;
        float s910 = p9 + p10;
        num[0] = core + (p1 + s23);            // p[1..8]
        num[1] = core + (s23 + p9);            // p[2..9]
        num[2] = core + (p3 + s910);           // p[3..10]
        num[3] = core + (s910 + p11);          // p[4..11]
    }
    float inv[4] = {ivv.x, ivv.y, ivv.z, ivv.w};

    float4 atv, apv;
    float* atf = (float*)&atv;
    float* apf = (float*)&apv;
#pragma unroll
    for (int c = 0; c < 4; c++) {
        float a_p = 0.f;
#pragma unroll
        for (int k = 0; k < Kv; k++)
            a_p = fmaf(ktr[k], xw[8 + c - k], a_p);
        float a_t = num[c] * inv[c];
        if (FIRST) {
            if (4 * j + c < Kv - 1) a_t = 0.f;   // BIG-sentinel mask
        }
        atf[c] = a_t;
        apf[c] = a_p;
        gr[0] = fmaf(a_t, a_t, gr[0]);
        gr[1] = fmaf(a_t, a_p, gr[1]);
        gr[2] = fmaf(a_p, a_p, gr[2]);
    }
    atv_o = atv;
    apv_o = apv;
}

__global__ void __launch_bounds__(TPB, 2) fused_kernel(
    const float* __restrict__ x,
    const float* __restrict__ kt,
    float* __restrict__ out)
{
    __shared__ float sred[16][3];
    __shared__ float scoef[2];

    const int bc  = blockIdx.x;            // b*Cv + c
    const int b   = bc >> 8;
    const int tid = threadIdx.x;
    const int lid = tid & 31;
    const int wid = tid >> 5;

    const float4* Er  = &g_E[(size_t)b * NJ];
    const float4* ivr = &g_inv[(size_t)b * NJ];
    const float4* xr  = (const float4*)(x + (size_t)bc * Lv);

    float ktr[Kv];
#pragma unroll
    for (int k = 0; k < Kv; k++) ktr[k] = __ldg(&kt[k]);

    float gr[3] = {0.f, 0.f, 0.f};
    float4 at0, ap0, at1, ap1;

    // Iteration 0 (halo zero-fill + l<7 mask live only here), iteration 1.
    pass1_iter<true >(tid,       Er, ivr, xr, ktr, gr, at0, ap0);
    pass1_iter<false>(tid + TPB, Er, ivr, xr, ktr, gr, at1, ap1);

    // ---- block reduction of 3 Gram scalars (only these cross threads) ----
#pragma unroll
    for (int q = 0; q < 3; q++) {
        float v = gr[q];
#pragma unroll
        for (int o = 16; o > 0; o >>= 1)
            v += __shfl_xor_sync(0xffffffffu, v, o);
        if (lid == 0) sred[wid][q] = v;
    }
    __syncthreads();
    if (tid == 0) {
        float G00 = 0.f, G01 = 0.f, G11 = 0.f;
#pragma unroll
        for (int wq = 0; wq < 16; wq++) {
            G00 += sred[wq][0];
            G01 += sred[wq][1];
            G11 += sred[wq][2];
        }
        // scores row0 = softmax([G00,G01]); row1 = softmax([G01,G11])
        // out = 0.5*((s00+s10)*at + ((1-s00)+(1-s10))*ap)
        float s00 = 1.0f / (1.0f + __expf(G01 - G00));
        float s10 = 1.0f / (1.0f + __expf(G11 - G01));
        scoef[0] = 0.5f * (s00 + s10);
        scoef[1] = 0.5f * ((1.0f - s00) + (1.0f - s10));
    }
    __syncthreads();

    // ---- pass 2: out = ca*at + cb*ap straight from registers ----
    const float ca = scoef[0];
    const float cb = scoef[1];
    float4* orow = (float4*)(out + (size_t)bc * Lv);
    float4 o0, o1;
    o0.x = fmaf(ca, at0.x, cb * ap0.x);
    o0.y = fmaf(ca, at0.y, cb * ap0.y);
    o0.z = fmaf(ca, at0.z, cb * ap0.z);
    o0.w = fmaf(ca, at0.w, cb * ap0.w);
    o1.x = fmaf(ca, at1.x, cb * ap1.x);
    o1.y = fmaf(ca, at1.y, cb * ap1.y);
    o1.z = fmaf(ca, at1.z, cb * ap1.z);
    o1.w = fmaf(ca, at1.w, cb * ap1.w);
    orow[tid]       = o0;
    orow[tid + TPB] = o1;
}

// ---------------------------------------------------------------------------
extern "C" void kernel_launch(void* const* d_in, const int* in_sizes, int n_in,
                              void* d_out, int out_size) {
    const float* x  = (const float*)d_in[0];   // (B, C, L) f32
    const float* dt = (const float*)d_in[1];   // (B, L)    f32
    const float* kt = (const float*)d_in[2];   // (1, 1, K) f32
    float* out = (float*)d_out;                // (B, C, L) f32

    precompute_kernel<<<Bv * NJ / 128, 128>>>(dt);
    fused_kernel<<<Bv * Cv, TPB>>>(x, kt, out);
}

// round 17
// speedup vs baseline: 1.2110x; 1.2110x over previous
#include <cuda_runtime.h>
#include <cuda_bf16.h>

// Problem shape (fixed by the dataset)
#define Bv 8
#define Cv 256
#define Lv 4096
#define Kv 8
#define Gv 2              // channels per CTA (share weight computation)
#define TPB 256
#define NJ (Lv / 4)       // float4s per row = 1024
#define ITERS (NJ / TPB)  // 4

#define NITEMS (Bv * Cv / Gv)   // 1024 row-pair work items
#define GRIDN  444               // 3 CTAs/SM x 148 SMs: zero wave quantization
#define EPOCH  (NITEMS + GRIDN)  // tickets consumed per launch (exact)

#define SMEM_BYTES (2 * Gv * Lv * 4)

// Monotone global ticket counter. Never reset: each launch consumes exactly
// EPOCH tickets (NITEMS work tickets + exactly one exit ticket per CTA), so
// (ticket % EPOCH) self-aligns across the correctness run and graph replays.
__device__ unsigned long long g_ticket = 0ULL;

// ---------------------------------------------------------------------------
// Math (unchanged from the 21.0us R9 kernel):
//  softmax identity  w_k(l) = E[l-k] / sum_k' E[l-k'],  E = exp(dt)
//  (exp(-dt[l]) base cancels -> 12 exps per 4 elements, shared by 2 channels)
//  windowed numerators num_c = sum_{m=c+1}^{c+8} E[m]*x[m] (shared products)
//  at = num * rcp(den);  at[l<7] = 0 exactly (reference BIG sentinel)
//  ap = sum_k kt[k] x[l-k]
// ---------------------------------------------------------------------------
template<bool FIRST>
__device__ __forceinline__ void pass1_iter(
    const int j,
    const float4* __restrict__ dtr,
    const float4* __restrict__ xr0,
    const float4* __restrict__ xr1,
    const float*  __restrict__ ktr,     // [Kv] in registers
    float4* __restrict__ sat,           // [Gv*NJ]
    float4* __restrict__ sap,           // [Gv*NJ]
    float*  __restrict__ gr)            // [Gv*3] Gram accumulators
{
    const float4 zero4 = make_float4(0.f, 0.f, 0.f, 0.f);

    // dt window [4j-8 .. 4j+3] -> E = exp(dt)
    float4 dm2 = FIRST ? ((j >= 2) ? dtr[j - 2] : zero4) : dtr[j - 2];
    float4 dm1 = FIRST ? ((j >= 1) ? dtr[j - 1] : zero4) : dtr[j - 1];
    float4 dd0 = dtr[j];
    float Ew[12] = {dm2.x, dm2.y, dm2.z, dm2.w,
                    dm1.x, dm1.y, dm1.z, dm1.w,
                    dd0.x, dd0.y, dd0.z, dd0.w};
#pragma unroll
    for (int m = 0; m < 12; m++) Ew[m] = __expf(Ew[m]);

    // reciprocal 8-tap sums (shared factored partials)
    float inv[4];
    {
        float c45  = Ew[4] + Ew[5];
        float c67  = Ew[6] + Ew[7];
        float core = (c45 + c67) + Ew[8];          // E[4..8]
        float s23  = Ew[2] + Ew[3];
        float s910 = Ew[9] + Ew[10];
        inv[0] = __fdividef(1.0f, core + (Ew[1] + s23));    // E[1..8]
        inv[1] = __fdividef(1.0f, core + (s23 + Ew[9]));    // E[2..9]
        inv[2] = __fdividef(1.0f, core + (Ew[3] + s910));   // E[3..10]
        inv[3] = __fdividef(1.0f, core + (s910 + Ew[11]));  // E[4..11]
    }

#pragma unroll
    for (int g = 0; g < Gv; g++) {
        const float4* xr = (g == 0) ? xr0 : xr1;
        float4 xm2 = FIRST ? ((j >= 2) ? xr[j - 2] : zero4) : xr[j - 2];
        float4 xm1 = FIRST ? ((j >= 1) ? xr[j - 1] : zero4) : xr[j - 1];
        float4 x0  = xr[j];
        float xw[12] = {xm2.x, xm2.y, xm2.z, xm2.w,
                        xm1.x, xm1.y, xm1.z, xm1.w,
                        x0.x,  x0.y,  x0.z,  x0.w};

        // products p[m] = E[m]*x[m]; windowed numerators (shared core)
        float num[4];
        {
            float p1 = Ew[1] * xw[1],  p2 = Ew[2] * xw[2],  p3 = Ew[3] * xw[3];
            float p4 = Ew[4] * xw[4],  p5 = Ew[5] * xw[5],  p6 = Ew[6] * xw[6];
            float p7 = Ew[7] * xw[7],  p8 = Ew[8] * xw[8],  p9 = Ew[9] * xw[9];
            float p10 = Ew[10] * xw[10], p11 = Ew[11] * xw[11];
            float c45  = p4 + p5;
            float c67  = p6 + p7;
            float core = (c45 + c67) + p8;         // p[4..8]
            float s23  = p2 + p3;
            float s910 = p9 + p10;
            num[0] = core + (p1 + s23);            // p[1..8]
            num[1] = core + (s23 + p9);            // p[2..9]
            num[2] = core + (p3 + s910);           // p[3..10]
            num[3] = core + (s910 + p11);          // p[4..11]
        }

        float4 atv, apv;
        float* atf = (float*)&atv;
        float* apf = (float*)&apv;
#pragma unroll
        for (int c = 0; c < 4; c++) {
            float a_p = 0.f;
#pragma unroll
            for (int k = 0; k < Kv; k++)
                a_p = fmaf(ktr[k], xw[8 + c - k], a_p);
            float a_t = num[c] * inv[c];
            if (FIRST) {
                if (4 * j + c < Kv - 1) a_t = 0.f;   // BIG-sentinel mask
            }
            atf[c] = a_t;
            apf[c] = a_p;
            gr[g * 3 + 0] = fmaf(a_t, a_t, gr[g * 3 + 0]);
            gr[g * 3 + 1] = fmaf(a_t, a_p, gr[g * 3 + 1]);
            gr[g * 3 + 2] = fmaf(a_p, a_p, gr[g * 3 + 2]);
        }
        sat[g * NJ + j] = atv;
        sap[g * NJ + j] = apv;
    }
}

__global__ void __launch_bounds__(TPB, 3) fused_kernel(
    const float* __restrict__ x,
    const float* __restrict__ dt,
    const float* __restrict__ kt,
    float* __restrict__ out)
{
    extern __shared__ float smem[];
    float4* sat = (float4*)smem;               // [Gv][NJ]
    float4* sap = (float4*)(smem + Gv * Lv);   // [Gv][NJ]
    __shared__ float sred[8][Gv * 3];
    __shared__ float scoef[Gv][2];
    __shared__ int   s_item;

    const int tid = threadIdx.x;
    const int lid = tid & 31;
    const int wid = tid >> 5;

    float ktr[Kv];
#pragma unroll
    for (int k = 0; k < Kv; k++) ktr[k] = __ldg(&kt[k]);

    // ---- persistent work-stealing loop over row-pair items ----
    for (;;) {
        if (tid == 0) {
            unsigned long long t = atomicAdd(&g_ticket, 1ULL);
            s_item = (int)(t % (unsigned long long)EPOCH);
        }
        __syncthreads();
        const int item = s_item;
        if (item >= NITEMS) break;             // this launch's exit ticket

        const int b  = item >> 7;              // / (Cv/Gv = 128)
        const int c0 = (item & 127) * Gv;

        const float4* dtr = (const float4*)(dt + (size_t)b * Lv);
        const float4* xr0 = (const float4*)(x + (size_t)(b * Cv + c0 + 0) * Lv);
        const float4* xr1 = (const float4*)(x + (size_t)(b * Cv + c0 + 1) * Lv);

        float gr[Gv * 3];
#pragma unroll
        for (int q = 0; q < Gv * 3; q++) gr[q] = 0.f;

        // Iteration 0 (peeled: halo zero-fill + l<7 mask live only here)
        pass1_iter<true>(tid, dtr, xr0, xr1, ktr, sat, sap, gr);
        // Iterations 1..3 (guard-free)
#pragma unroll 1
        for (int i = 1; i < ITERS; i++)
            pass1_iter<false>(tid + i * TPB, dtr, xr0, xr1, ktr, sat, sap, gr);

        // ---- block reduction of 6 Gram scalars ----
#pragma unroll
        for (int q = 0; q < Gv * 3; q++) {
            float v = gr[q];
#pragma unroll
            for (int o = 16; o > 0; o >>= 1)
                v += __shfl_xor_sync(0xffffffffu, v, o);
            if (lid == 0) sred[wid][q] = v;
        }
        __syncthreads();
        if (tid < Gv) {
            float G00 = 0.f, G01 = 0.f, G11 = 0.f;
#pragma unroll
            for (int wq = 0; wq < 8; wq++) {
                G00 += sred[wq][tid * 3 + 0];
                G01 += sred[wq][tid * 3 + 1];
                G11 += sred[wq][tid * 3 + 2];
            }
            // scores row0 = softmax([G00,G01]); row1 = softmax([G01,G11])
            // out = 0.5*((s00+s10)*at + ((1-s00)+(1-s10))*ap)
            float s00 = 1.0f / (1.0f + __expf(G01 - G00));
            float s10 = 1.0f / (1.0f + __expf(G11 - G01));
            scoef[tid][0] = 0.5f * (s00 + s10);
            scoef[tid][1] = 0.5f * ((1.0f - s00) + (1.0f - s10));
        }
        __syncthreads();

        // ---- pass 2: out = ca*at + cb*ap (LDS.128 -> STG.128) ----
#pragma unroll
        for (int g = 0; g < Gv; g++) {
            const float ca = scoef[g][0];
            const float cb = scoef[g][1];
            float4* orow = (float4*)(out + (size_t)(b * Cv + c0 + g) * Lv);
#pragma unroll
            for (int i = 0; i < ITERS; i++) {
                const int j = tid + i * TPB;
                float4 a = sat[g * NJ + j];
                float4 p = sap[g * NJ + j];
                float4 o;
                o.x = fmaf(ca, a.x, cb * p.x);
                o.y = fmaf(ca, a.y, cb * p.y);
                o.z = fmaf(ca, a.z, cb * p.z);
                o.w = fmaf(ca, a.w, cb * p.w);
                orow[j] = o;
            }
        }
        // next loop iteration's top barrier orders smem reuse
    }
}

// ---------------------------------------------------------------------------
extern "C" void kernel_launch(void* const* d_in, const int* in_sizes, int n_in,
                              void* d_out, int out_size) {
    const float* x  = (const float*)d_in[0];   // (B, C, L) f32
    const float* dt = (const float*)d_in[1];   // (B, L)    f32
    const float* kt = (const float*)d_in[2];   // (1, 1, K) f32
    float* out = (float*)d_out;                // (B, C, L) f32

    cudaFuncSetAttribute(fused_kernel,
                         cudaFuncAttributeMaxDynamicSharedMemorySize, SMEM_BYTES);

    fused_kernel<<<GRIDN, TPB, SMEM_BYTES>>>(x, dt, kt, out);
}